// round 13
// baseline (speedup 1.0000x reference)
#include <cuda_runtime.h>
#include <math.h>
#include <float.h>

#define THREADS 256
#define GRID 592          // 4 * 148 SMs -> exactly one resident wave at occupancy 4
#define BX 72
#define BY 40
#define NBIN (BX * BY)
#define SHAD 4            // shadow counters per bin (atomic contention /4)
#define NBIN2 (NBIN * SHAD)
#define MAXPTS 1048576
#define NCORN 128

// Zero-initialized scratch; kernel self-restores zeros after each run
// (graph-replay deterministic, no init kernel needed).
__device__ unsigned int g_cmax[NCORN];   // key = ~fenc(min d2) ; 0 == "empty"
__device__ unsigned int g_ctr;
__device__ unsigned int g_bar;           // grid-barrier counter (monotone per run)
__device__ int g_cnt[NBIN2];             // per-shadow-bin counts
__device__ int g_cur[NBIN2];             // scatter cursors
__device__ int g_off[NBIN2 + 1];         // exclusive prefix (rewritten each run)
__device__ __align__(16) float2 g_pt[MAXPTS];  // binned (u, v_final)

// Robustly read a dimension that might arrive as int32/int64 or float32.
__device__ __forceinline__ float read_dim(const void* p) {
    int iv = *(const int*)p;                // little-endian: also low word of int64
    if (iv > 0 && iv < 1000000) return (float)iv;
    return *(const float*)p;
}

// Monotone total-order encoding of float -> unsigned (handles negatives).
__device__ __forceinline__ unsigned fenc(float f) {
    unsigned b = __float_as_uint(f);
    return (b & 0x80000000u) ? ~b : (b | 0x80000000u);
}
__device__ __forceinline__ float fdec(unsigned k) {
    return __uint_as_float((k & 0x80000000u) ? (k ^ 0x80000000u) : ~k);
}

struct Cam {
    float R00, R01, R02, R10, R11, R12, R20, R21, R22;
    float camx, camy, camz, f, kx0, ky0, Hf;
};

// fp32 camera setup mirroring the reference float32 pipeline.
__device__ __forceinline__ Cam make_cam(const float* cam, const float* theta,
                                        const float* va, const void* hp, const void* wp,
                                        float& Wf_out) {
    Cam C;
    const float d2rf = 0.017453292519943295f;
    float rx = __fmul_rn(theta[0], d2rf);
    float ry = __fmul_rn(theta[1], d2rf);
    float rz = __fmul_rn(theta[2], d2rf);
    float cxa = cosf(rx), sxa = sinf(rx);
    float cya = cosf(ry), sya = sinf(ry);
    float cza = cosf(rz), sza = sinf(rz);
    float M01 = __fmul_rn(sya, sxa), M02 = __fmul_rn(sya, cxa);
    float M11 = cxa,                 M12 = -sxa;
    C.R20 = -sya; C.R21 = __fmul_rn(cya, sxa); C.R22 = __fmul_rn(cya, cxa);
    C.R00 = __fmul_rn(cza, cya);
    C.R01 = __fsub_rn(__fmul_rn(cza, M01), __fmul_rn(sza, M11));
    C.R02 = __fsub_rn(__fmul_rn(cza, M02), __fmul_rn(sza, M12));
    C.R10 = __fmul_rn(sza, cya);
    C.R11 = __fadd_rn(__fmul_rn(sza, M01), __fmul_rn(cza, M11));
    C.R12 = __fadd_rn(__fmul_rn(sza, M02), __fmul_rn(cza, M12));
    C.Hf = read_dim(hp);
    Wf_out = read_dim(wp);
    float vr = __fmul_rn(__fmul_rn(va[0], 0.5f), d2rf);
    C.f   = __fdiv_rn(-C.Hf, __fmul_rn(2.0f, tanf(vr)));
    C.kx0 = __fsub_rn(__fmul_rn(Wf_out, 0.5f), 0.5f);
    C.ky0 = __fsub_rn(__fmul_rn(C.Hf, 0.5f), 0.5f);
    C.camx = cam[0]; C.camy = cam[1]; C.camz = cam[2];
    return C;
}

// Project one point: returns (u, v_final). Rounding replicates the reference.
__device__ __forceinline__ float2 project(const Cam& C, const float* pp) {
    float tx = __fadd_rn(pp[0], -C.camx);
    float ty = __fadd_rn(pp[1], -C.camy);
    float tz = __fadd_rn(pp[2], -C.camz);
    float x = __fmaf_rn(tz, C.R02, __fmaf_rn(ty, C.R01, __fmul_rn(tx, C.R00)));
    float y = __fmaf_rn(tz, C.R12, __fmaf_rn(ty, C.R11, __fmul_rn(tx, C.R10)));
    float z = __fmaf_rn(tz, C.R22, __fmaf_rn(ty, C.R21, __fmul_rn(tx, C.R20)));
    float xp = __fdiv_rn(x, z);
    float yp = __fdiv_rn(y, z);
    float u  = __fmaf_rn(C.f, xp, C.kx0);
    float v  = __fmaf_rn(C.f, yp, C.ky0);
    float vf = __fadd_rn(C.Hf, -v);
    return make_float2(u, vf);
}

// Grid-wide barrier (all GRID blocks co-resident by construction).
__device__ __forceinline__ void gridbar(unsigned target) {
    __threadfence();
    __syncthreads();
    if (threadIdx.x == 0) {
        atomicAdd(&g_bar, 1u);
        while (*((volatile unsigned int*)&g_bar) < target) __nanosleep(32);
    }
    __syncthreads();
    __threadfence();
}

__global__ void __launch_bounds__(THREADS, 4)
k_main(const float* __restrict__ P, const float* __restrict__ dtc,
       const float* __restrict__ cam, const float* __restrict__ theta,
       const float* __restrict__ va, const void* hp, const void* wp,
       int N, float* __restrict__ out) {
    __shared__ int   tpart[THREADS];
    __shared__ float swarp[8];
    __shared__ bool  isLast;
    __shared__ float red[NCORN];

    const int tid = threadIdx.x;
    const int bid = blockIdx.x;

    float Wf;
    const Cam C = make_cam(cam, theta, va, hp, wp, Wf);

    // Binning grid: 3W x 3H window centered on the image; clamped borders.
    const float gx0 = -Wf, gy0 = -C.Hf;
    const float icw = (float)BX / (3.0f * Wf);
    const float ich = (float)BY / (3.0f * C.Hf);
    const float cellmin = fminf(3.0f * Wf / (float)BX, 3.0f * C.Hf / (float)BY);

    const int ppb = (N + GRID - 1) / GRID;
    const int i0  = bid * ppb;
    const int i1  = min(N, i0 + ppb);
    const int sh  = bid & (SHAD - 1);

    // ---- Phase 1: count points per shadow bin ----
    for (int i = i0 + tid; i < i1; i += THREADS) {
        float2 q = project(C, P + 3 * i);
        int bu = (int)(__fmul_rn(__fadd_rn(q.x, -gx0), icw));
        int bv = (int)(__fmul_rn(__fadd_rn(q.y, -gy0), ich));
        bu = max(0, min(BX - 1, bu));
        bv = max(0, min(BY - 1, bv));
        atomicAdd(&g_cnt[(bv * BX + bu) * SHAD + sh], 1);
    }
    gridbar(GRID);

    // ---- Phase 2: block 0 computes exclusive prefix over shadow bins ----
    if (bid == 0) {
        const int chunk = (NBIN2 + THREADS - 1) / THREADS;   // 45
        const int b0 = tid * chunk, b1 = min(NBIN2, b0 + chunk);
        int sum = 0;
        for (int b = b0; b < b1; b++) sum += g_cnt[b];
        tpart[tid] = sum;
        __syncthreads();
        int val = sum;
        for (int o = 1; o < THREADS; o <<= 1) {
            int other = (tid >= o) ? tpart[tid - o] : 0;
            __syncthreads();
            val += other;
            tpart[tid] = val;
            __syncthreads();
        }
        int run = val - sum;     // exclusive prefix of this thread's chunk
        for (int b = b0; b < b1; b++) { g_off[b] = run; run += g_cnt[b]; }
        if (tid == THREADS - 1) g_off[NBIN2] = run;
    }
    gridbar(2u * GRID);

    // ---- Phase 3: scatter (u, v) into bin-sorted order ----
    for (int i = i0 + tid; i < i1; i += THREADS) {
        float2 q = project(C, P + 3 * i);
        int bu = (int)(__fmul_rn(__fadd_rn(q.x, -gx0), icw));
        int bv = (int)(__fmul_rn(__fadd_rn(q.y, -gy0), ich));
        bu = max(0, min(BX - 1, bu));
        bv = max(0, min(BY - 1, bv));
        int b2 = (bv * BX + bu) * SHAD + sh;
        int pos = g_off[b2] + atomicAdd(&g_cur[b2], 1);
        g_pt[pos] = q;
    }
    gridbar(3u * GRID);

    // ---- Phase 4: corner ring search (blocks 0..127) / cleanup (rest) ----
    if (bid >= NCORN) {
        for (int i = (bid - NCORN) * THREADS + tid; i < NBIN2;
             i += (GRID - NCORN) * THREADS) {
            g_cnt[i] = 0;
            g_cur[i] = 0;
        }
    } else {
        const int c = bid;
        const float ccx = dtc[2 * c], ccy = dtc[2 * c + 1];
        const float t1 = __fadd_rn(__fmul_rn(ccx, ccx), __fmul_rn(ccy, ccy));
        int bcu = (int)(__fmul_rn(__fadd_rn(ccx, -gx0), icw));
        int bcv = (int)(__fmul_rn(__fadd_rn(ccy, -gy0), ich));
        bcu = max(0, min(BX - 1, bcu));
        bcv = max(0, min(BY - 1, bcv));

        float lbest = 3.4e38f;   // per-thread running min over scanned candidates
        float gbest = 3.4e38f;   // block-wide min (valid after each ring reduce)
        const int rmax = (BX > BY ? BX : BY);

        for (int r = 0; r <= rmax; r++) {
            // Scan ring r (uniform control flow across the block).
            const int xlo = bcu - r, xhi = bcu + r;
            const int ylo = bcv - r, yhi = bcv + r;
            for (int y = ylo; y <= yhi; y++) {
                if (y < 0 || y >= BY) continue;
                const bool edge_row = (y == ylo || y == yhi);
                const int xstep = edge_row ? 1 : (xhi - xlo > 0 ? xhi - xlo : 1);
                for (int x = xlo; x <= xhi; x += xstep) {
                    if (x < 0 || x >= BX) continue;
                    const int b = (y * BX + x) * SHAD;
                    const int o0 = g_off[b], o1 = g_off[b + SHAD];
                    for (int idx = o0 + tid; idx < o1; idx += THREADS) {
                        float2 p = g_pt[idx];
                        float s   = __fadd_rn(__fmul_rn(p.x, p.x), __fmul_rn(p.y, p.y));
                        float t1s = __fadd_rn(t1, s);
                        float dot = __fmaf_rn(ccy, p.y, __fmul_rn(ccx, p.x));
                        float d2  = __fmaf_rn(-2.0f, dot, t1s);
                        lbest = fminf(lbest, d2);
                    }
                }
            }
            // Block-wide min of accumulated candidates.
            float v = lbest;
            for (int o = 16; o >= 1; o >>= 1)
                v = fminf(v, __shfl_xor_sync(0xFFFFFFFFu, v, o));
            if ((tid & 31) == 0) swarp[tid >> 5] = v;
            __syncthreads();
            if (tid < 8) {
                float w = swarp[tid];
                for (int o = 4; o >= 1; o >>= 1)
                    w = fminf(w, __shfl_xor_sync(0xFFu, w, o));
                if (tid == 0) swarp[0] = w;
            }
            __syncthreads();
            gbest = swarp[0];
            __syncthreads();

            // Unscanned points lie in rings > r: coordinate distance >= r*cellmin.
            float lb = (float)r * cellmin;
            if (__fmul_rn(lb, lb) > gbest + 64.0f) break;
        }
        if (tid == 0) atomicMax(&g_cmax[c], ~fenc(gbest));
    }

    // ---- Final: last block sums the 128 minima + restores scratch ----
    __threadfence();
    __syncthreads();
    if (tid == 0) {
        unsigned old = atomicAdd(&g_ctr, 1u);
        isLast = (old == gridDim.x - 1u);
    }
    __syncthreads();
    if (isLast) {
        if (tid < NCORN) {
            red[tid] = fdec(~g_cmax[tid]);
            g_cmax[tid] = 0u;               // restore for next (graph) replay
        }
        if (tid == 0) { g_ctr = 0u; g_bar = 0u; }
        __syncthreads();
        for (int off = 64; off > 0; off >>= 1) {
            if (tid < off) red[tid] += red[tid + off];
            __syncthreads();
        }
        if (tid == 0) out[0] = red[0];
    }
}

extern "C" void kernel_launch(void* const* d_in, const int* in_sizes, int n_in,
                              void* d_out, int out_size) {
    const float* PntCld = (const float*)d_in[0];
    const float* dtcCor = (const float*)d_in[1];
    const float* cam    = (const float*)d_in[2];
    const float* theta  = (const float*)d_in[3];
    const float* va     = (const float*)d_in[4];
    const void*  hp     = d_in[5];
    const void*  wp     = d_in[6];

    int N = in_sizes[0] / 3;
    if (N > MAXPTS) N = MAXPTS;

    k_main<<<GRID, THREADS>>>(PntCld, dtcCor, cam, theta, va, hp, wp,
                              N, (float*)d_out);
}

// round 14
// speedup vs baseline: 1.8061x; 1.8061x over previous
#include <cuda_runtime.h>
#include <math.h>

#define THREADS 256
#define GRID 592          // 4 * 148 SMs -> exactly one resident wave at occupancy 4
#define BX 144
#define BY 80
#define NBIN (BX * BY)    // 11520 cells, ~40x40.5 px each over the 3W x 3H window
#define CAP 1024          // per-cell capacity (expected peak ~470)
#define MAXPTS 1048576
#define NCORN 128

// Zero-initialized scratch; kernel self-restores zeros after each run.
__device__ unsigned int g_cmax[NCORN];   // key = ~fenc(min d2); 0 == "empty"
__device__ unsigned int g_ctr;
__device__ unsigned int g_bar;
__device__ int g_cnt[NBIN];
__device__ int g_farc;                   // out-of-window points
__device__ int g_ovfc;                   // cell-overflow points
__device__ __align__(16) float2 g_bin[(size_t)NBIN * CAP];
__device__ __align__(16) float2 g_far[MAXPTS];
__device__ __align__(16) float2 g_ovf[MAXPTS];

__device__ __forceinline__ float read_dim(const void* p) {
    int iv = *(const int*)p;
    if (iv > 0 && iv < 1000000) return (float)iv;
    return *(const float*)p;
}

__device__ __forceinline__ unsigned fenc(float f) {
    unsigned b = __float_as_uint(f);
    return (b & 0x80000000u) ? ~b : (b | 0x80000000u);
}
__device__ __forceinline__ float fdec(unsigned k) {
    return __uint_as_float((k & 0x80000000u) ? (k ^ 0x80000000u) : ~k);
}

struct Cam {
    float R00, R01, R02, R10, R11, R12, R20, R21, R22;
    float camx, camy, camz, f, kx0, ky0, Hf;
};

__device__ __forceinline__ Cam make_cam(const float* cam, const float* theta,
                                        const float* va, const void* hp, const void* wp,
                                        float& Wf_out) {
    Cam C;
    const float d2rf = 0.017453292519943295f;
    float rx = __fmul_rn(theta[0], d2rf);
    float ry = __fmul_rn(theta[1], d2rf);
    float rz = __fmul_rn(theta[2], d2rf);
    float cxa = cosf(rx), sxa = sinf(rx);
    float cya = cosf(ry), sya = sinf(ry);
    float cza = cosf(rz), sza = sinf(rz);
    float M01 = __fmul_rn(sya, sxa), M02 = __fmul_rn(sya, cxa);
    float M11 = cxa,                 M12 = -sxa;
    C.R20 = -sya; C.R21 = __fmul_rn(cya, sxa); C.R22 = __fmul_rn(cya, cxa);
    C.R00 = __fmul_rn(cza, cya);
    C.R01 = __fsub_rn(__fmul_rn(cza, M01), __fmul_rn(sza, M11));
    C.R02 = __fsub_rn(__fmul_rn(cza, M02), __fmul_rn(sza, M12));
    C.R10 = __fmul_rn(sza, cya);
    C.R11 = __fadd_rn(__fmul_rn(sza, M01), __fmul_rn(cza, M11));
    C.R12 = __fadd_rn(__fmul_rn(sza, M02), __fmul_rn(cza, M12));
    C.Hf = read_dim(hp);
    Wf_out = read_dim(wp);
    float vr = __fmul_rn(__fmul_rn(va[0], 0.5f), d2rf);
    C.f   = __fdiv_rn(-C.Hf, __fmul_rn(2.0f, tanf(vr)));
    C.kx0 = __fsub_rn(__fmul_rn(Wf_out, 0.5f), 0.5f);
    C.ky0 = __fsub_rn(__fmul_rn(C.Hf, 0.5f), 0.5f);
    C.camx = cam[0]; C.camy = cam[1]; C.camz = cam[2];
    return C;
}

__device__ __forceinline__ float2 project(const Cam& C, const float* pp) {
    float tx = __fadd_rn(pp[0], -C.camx);
    float ty = __fadd_rn(pp[1], -C.camy);
    float tz = __fadd_rn(pp[2], -C.camz);
    float x = __fmaf_rn(tz, C.R02, __fmaf_rn(ty, C.R01, __fmul_rn(tx, C.R00)));
    float y = __fmaf_rn(tz, C.R12, __fmaf_rn(ty, C.R11, __fmul_rn(tx, C.R10)));
    float z = __fmaf_rn(tz, C.R22, __fmaf_rn(ty, C.R21, __fmul_rn(tx, C.R20)));
    float xp = __fdiv_rn(x, z);
    float yp = __fdiv_rn(y, z);
    float u  = __fmaf_rn(C.f, xp, C.kx0);
    float v  = __fmaf_rn(C.f, yp, C.ky0);
    float vf = __fadd_rn(C.Hf, -v);
    return make_float2(u, vf);
}

// d2 with the reference rounding chain (identical to all prior passing rounds).
__device__ __forceinline__ float dist2(float ccx, float ccy, float t1, float2 p) {
    float s   = __fadd_rn(__fmul_rn(p.x, p.x), __fmul_rn(p.y, p.y));
    float t1s = __fadd_rn(t1, s);
    float dot = __fmaf_rn(ccy, p.y, __fmul_rn(ccx, p.x));
    return __fmaf_rn(-2.0f, dot, t1s);
}

__global__ void __launch_bounds__(THREADS, 4)
k_main(const float* __restrict__ P, const float* __restrict__ dtc,
       const float* __restrict__ cam, const float* __restrict__ theta,
       const float* __restrict__ va, const void* hp, const void* wp,
       int N, float* __restrict__ out) {
    __shared__ float swarp[8];
    __shared__ float sbest;
    __shared__ bool  isLast;
    __shared__ float red[NCORN];

    const int tid = threadIdx.x;
    const int bid = blockIdx.x;

    float Wf;
    const Cam C = make_cam(cam, theta, va, hp, wp, Wf);

    const float gx0 = -Wf, gy0 = -C.Hf;
    const float icw = __fdiv_rn((float)BX, 3.0f * Wf);
    const float ich = __fdiv_rn((float)BY, 3.0f * C.Hf);
    const float cellmin = fminf(__fdiv_rn(3.0f * Wf, (float)BX),
                                __fdiv_rn(3.0f * C.Hf, (float)BY));

    // ---- Phase 1: project + direct-bucket scatter (each point once) ----
    const int ppb = (N + GRID - 1) / GRID;
    const int i0  = bid * ppb;
    const int i1  = min(N, i0 + ppb);
    for (int i = i0 + tid; i < i1; i += THREADS) {
        float2 q = project(C, P + 3 * i);
        float fx = __fmul_rn(__fadd_rn(q.x, -gx0), icw);
        float fy = __fmul_rn(__fadd_rn(q.y, -gy0), ich);
        if (fx >= 0.0f && fx < (float)BX && fy >= 0.0f && fy < (float)BY) {
            int cell = (int)fy * BX + (int)fx;
            int pos = atomicAdd(&g_cnt[cell], 1);
            if (pos < CAP) g_bin[(size_t)cell * CAP + pos] = q;
            else { int op = atomicAdd(&g_ovfc, 1); if (op < MAXPTS) g_ovf[op] = q; }
        } else {
            int fp = atomicAdd(&g_farc, 1); if (fp < MAXPTS) g_far[fp] = q;
        }
    }

    // ---- Single grid-wide barrier (all 592 blocks co-resident) ----
    __threadfence();
    __syncthreads();
    if (tid == 0) {
        atomicAdd(&g_bar, 1u);
        while (*((volatile unsigned int*)&g_bar) < (unsigned)gridDim.x) __nanosleep(32);
    }
    __syncthreads();
    __threadfence();

    // ---- Phase 2: blocks 0..127 each resolve one corner ----
    if (bid < NCORN) {
        const float ccx = dtc[2 * bid], ccy = dtc[2 * bid + 1];
        const float t1 = __fadd_rn(__fmul_rn(ccx, ccx), __fmul_rn(ccy, ccy));
        int bcu = (int)(__fmul_rn(__fadd_rn(ccx, -gx0), icw));
        int bcv = (int)(__fmul_rn(__fadd_rn(ccy, -gy0), ich));
        bcu = max(0, min(BX - 1, bcu));
        bcv = max(0, min(BY - 1, bcv));

        float lbest = 3.4e38f;

        // Overflow list (normally empty) must always be included for exactness.
        const int novf = min(g_ovfc, MAXPTS);
        for (int idx = tid; idx < novf; idx += THREADS)
            lbest = fminf(lbest, dist2(ccx, ccy, t1, g_ovf[idx]));

        // 3x3 cell block (rings 0..1): prefetch counts, then scan.
        int cells[9], cnts[9];
#pragma unroll
        for (int dy = -1; dy <= 1; dy++) {
#pragma unroll
            for (int dx = -1; dx <= 1; dx++) {
                int ii = (dy + 1) * 3 + (dx + 1);
                int x = bcu + dx, y = bcv + dy;
                bool ok = (x >= 0 && x < BX && y >= 0 && y < BY);
                cells[ii] = ok ? (y * BX + x) : 0;
                cnts[ii]  = ok ? min(g_cnt[cells[ii]], CAP) : 0;
            }
        }
#pragma unroll
        for (int ii = 0; ii < 9; ii++) {
            const size_t base = (size_t)cells[ii] * CAP;
            for (int idx = tid; idx < cnts[ii]; idx += THREADS)
                lbest = fminf(lbest, dist2(ccx, ccy, t1, g_bin[base + idx]));
        }

        // Block-wide reduce helper (inlined; executed uniformly).
        auto block_min = [&](float v) -> float {
            for (int o = 16; o >= 1; o >>= 1)
                v = fminf(v, __shfl_xor_sync(0xFFFFFFFFu, v, o));
            if ((tid & 31) == 0) swarp[tid >> 5] = v;
            __syncthreads();
            if (tid < 8) {
                float w = swarp[tid];
                for (int o = 4; o >= 1; o >>= 1)
                    w = fminf(w, __shfl_xor_sync(0xFFu, w, o));
                if (tid == 0) sbest = w;
            }
            __syncthreads();
            float r = sbest;
            __syncthreads();
            return r;
        };

        float gbest = block_min(lbest);

        // Outer rings (rare): unscanned cells at chebyshev > r are >= r*cellmin away.
        if (!(__fmul_rn(cellmin, cellmin) > gbest + 64.0f)) {
            const int rmax = (BX > BY ? BX : BY);
            for (int r = 2; r <= rmax; r++) {
                const int xlo = bcu - r, xhi = bcu + r;
                const int ylo = bcv - r, yhi = bcv + r;
                for (int y = ylo; y <= yhi; y++) {
                    if (y < 0 || y >= BY) continue;
                    const bool edge = (y == ylo || y == yhi);
                    const int step = edge ? 1 : (xhi - xlo);
                    for (int x = xlo; x <= xhi; x += step) {
                        if (x < 0 || x >= BX) continue;
                        const int cell = y * BX + x;
                        const int cnt = min(g_cnt[cell], CAP);
                        const size_t base = (size_t)cell * CAP;
                        for (int idx = tid; idx < cnt; idx += THREADS)
                            lbest = fminf(lbest, dist2(ccx, ccy, t1, g_bin[base + idx]));
                    }
                }
                gbest = block_min(lbest);
                float lb = __fmul_rn((float)r, cellmin);
                if (__fmul_rn(lb, lb) > gbest + 64.0f) break;
            }
        }

        // Far-points fallback: only if the window-edge bound could bind (never, in practice).
        float fbx = fminf(__fadd_rn(ccx, Wf), __fsub_rn(2.0f * Wf, ccx));
        float fby = fminf(__fadd_rn(ccy, C.Hf), __fsub_rn(2.0f * C.Hf, ccy));
        float fb  = fminf(fbx, fby);
        bool need_far = !(fb > 0.0f) || (gbest + 64.0f >= __fmul_rn(fb, fb));
        if (need_far) {
            const int nfar = min(g_farc, MAXPTS);
            for (int idx = tid; idx < nfar; idx += THREADS)
                lbest = fminf(lbest, dist2(ccx, ccy, t1, g_far[idx]));
            gbest = block_min(lbest);
        }

        if (tid == 0) atomicMax(&g_cmax[bid], ~fenc(gbest));
    }

    // ---- Final: last block sums minima + restores ALL scratch to zero ----
    __threadfence();
    __syncthreads();
    if (tid == 0) {
        unsigned old = atomicAdd(&g_ctr, 1u);
        isLast = (old == gridDim.x - 1u);
    }
    __syncthreads();
    if (isLast) {
        if (tid < NCORN) {
            red[tid] = fdec(~g_cmax[tid]);
            g_cmax[tid] = 0u;
        }
        for (int b = tid; b < NBIN; b += THREADS) g_cnt[b] = 0;
        if (tid == 0) { g_ctr = 0u; g_bar = 0u; g_farc = 0; g_ovfc = 0; }
        __syncthreads();
        for (int off = 64; off > 0; off >>= 1) {
            if (tid < off) red[tid] += red[tid + off];
            __syncthreads();
        }
        if (tid == 0) out[0] = red[0];
    }
}

extern "C" void kernel_launch(void* const* d_in, const int* in_sizes, int n_in,
                              void* d_out, int out_size) {
    const float* PntCld = (const float*)d_in[0];
    const float* dtcCor = (const float*)d_in[1];
    const float* cam    = (const float*)d_in[2];
    const float* theta  = (const float*)d_in[3];
    const float* va     = (const float*)d_in[4];
    const void*  hp     = d_in[5];
    const void*  wp     = d_in[6];

    int N = in_sizes[0] / 3;
    if (N > MAXPTS) N = MAXPTS;

    k_main<<<GRID, THREADS>>>(PntCld, dtcCor, cam, theta, va, hp, wp,
                              N, (float*)d_out);
}